// round 9
// baseline (speedup 1.0000x reference)
#include <cuda_runtime.h>
#include <cuda_bf16.h>

// RoPE: x[8, 4096, 1024] fp32, token_positions[4096] int32/int64.
// PERSISTENT variant of the proven R4 kernel: grid = 608 CTAs (152 SM x 4
// resident), each CTA grid-strides over the 4096 row-tiles -> single wave,
// no wave-transition overhead, 3488 fewer block launches. Per-tile body is
// byte-identical to R4: MLP=8 front-batched 128b loads, default cache policy
// (R6/R7 proved ldcs/stcs destroy cross-replay L2 reuse), sincos amortized
// over the 8 batches, Cody-Waite + __sincosf.

#define S_DIM 4096
#define D_DIM 1024
#define B_DIM 8
#define COLS  (D_DIM / 4)          // 256 float4 columns per row
#define SC    (S_DIM * COLS)       // float4s per batch = 1,048,576
#define NTILES S_DIM               // one tile = one (s) row = 256 float4 cols
#define GRID  608                  // 152 SMs * 4 resident CTAs

// ---- compile-time inv_freq table (double precision, <1e-14 rel err) ----
constexpr double cexp_taylor(double r) {
    double term = 1.0, sum = 1.0;
    for (int i = 1; i <= 26; ++i) { term *= r / (double)i; sum += term; }
    return sum;
}
constexpr double cexp(double x) {
    double t = x * 1.4426950408889634074;      // x / ln2
    int n = (int)(t >= 0.0 ? t + 0.5 : t - 0.5);
    double r = x - (double)n * 0.69314718055994530942;
    double e = cexp_taylor(r);
    double s = 1.0;
    int m = n < 0 ? -n : n;
    for (int i = 0; i < m; ++i) s *= 2.0;
    return n < 0 ? e / s : e * s;
}
struct alignas(16) FreqTable { float v[D_DIM / 2]; };
constexpr FreqTable make_table() {
    FreqTable t{};
    for (int k = 0; k < D_DIM / 2; ++k) {
        // 10000^(-k/512) = exp(-k * ln(10000)/512)
        t.v[k] = (float)cexp(-(9.2103403719761827361 / 512.0) * (double)k);
    }
    return t;
}
__device__ static const FreqTable g_tab = make_table();

__global__ void __launch_bounds__(256, 4) rope_kernel(
    const float4* __restrict__ x,
    const int* __restrict__ posw,     // raw 32-bit words of token_positions
    float4* __restrict__ out)
{
    // Dtype-robust position format probe (uniform, L1-resident after tile 1):
    // int64 LE buffer = [0,0,1,0,2,0,..] (word[1]==0); int32 = [0,1,2,..].
    const int is64 = (posw[1] == 0);
    const int c = threadIdx.x & 255;                 // float4 column (fixed)
    const float2 f = ((const float2*)g_tab.v)[c];    // inv_freq[2c], [2c+1]

    for (int t = blockIdx.x; t < NTILES; t += GRID) {
        const int idx = t * 256 + (int)threadIdx.x - (int)(threadIdx.x & ~255u)
                        + (int)(threadIdx.x & 255u) * 0;  // = t*256 + c
        const int i = t * 256 + c;
        const int s = t;                              // sequence position

        // Front-batch all 8 independent 128b loads (one per batch) so DRAM
        // latency overlaps the trig chain below. Default cache policy.
        float4 v[B_DIM];
        #pragma unroll
        for (int b = 0; b < B_DIM; b++) v[b] = x[b * SC + i];

        const float p = (float)posw[is64 ? (2 * s) : s];

        float a0 = p * f.x;
        float a1 = p * f.y;

        // 2-term Cody-Waite reduction mod 2*pi (n <= 652, n*C1 exact).
        const float INV_2PI = 0.15915494309189535f;
        const float C1 = 6.28125f;
        const float C2 = 1.9353071795864769e-3f;
        float n0 = rintf(a0 * INV_2PI);
        float n1 = rintf(a1 * INV_2PI);
        float r0 = fmaf(n0, -C1, a0); r0 = fmaf(n0, -C2, r0);
        float r1 = fmaf(n1, -C1, a1); r1 = fmaf(n1, -C2, r1);

        float s0, c0, s1, c1;
        __sincosf(r0, &s0, &c0);
        __sincosf(r1, &s1, &c1);

        #pragma unroll
        for (int b = 0; b < B_DIM; b++) {
            float4 o;
            o.x = c0 * v[b].x - s0 * v[b].y;
            o.y = s0 * v[b].x + c0 * v[b].y;
            o.z = c1 * v[b].z - s1 * v[b].w;
            o.w = s1 * v[b].z + c1 * v[b].w;
            out[b * SC + i] = o;          // default policy: cross-replay
        }                                  // L2 write coalescing
        (void)idx;
    }
}

extern "C" void kernel_launch(void* const* d_in, const int* in_sizes, int n_in,
                              void* d_out, int out_size)
{
    // Robust input binding: x has 33,554,432 elements, token_positions 4096.
    const float* xf  = nullptr;
    const int*   pos = nullptr;
    if (n_in >= 2 && in_sizes[0] <= S_DIM) {
        pos = (const int*)d_in[0];
        xf  = (const float*)d_in[1];
    } else {
        xf  = (const float*)d_in[0];
        pos = (const int*)d_in[1];
    }
    float4* out = (float4*)d_out;
    (void)out_size;

    rope_kernel<<<GRID, 256>>>((const float4*)xf, pos, out);
}

// round 10
// speedup vs baseline: 1.0660x; 1.0660x over previous
#include <cuda_runtime.h>
#include <cuda_bf16.h>

// RoPE: x[8, 4096, 1024] fp32, token_positions[4096] int32/int64.
// MLP=16 variant of the proven R4 kernel (the only lever that ever helped:
// R3 MLP~2 -> R4 MLP=8 raised DRAM 71.5%->75.8%). Each thread owns TWO
// float4 columns of one row (h and h+128; both warp-streams coalesced 128B),
// front-batches all 16 independent LDG.128s, computes 2 sincos pairs, then
// rotates+stores all 16. Default cache policy (R6/R7: hints destroy
// cross-replay L2 reuse). launch_bounds(256,3) -> 85-reg cap, no spills.

#define S_DIM 4096
#define D_DIM 1024
#define B_DIM 8
#define COLS  (D_DIM / 4)          // 256 float4 columns per row
#define SC    (S_DIM * COLS)       // float4s per batch = 1,048,576
#define HALF  128                   // columns per thread-half

// ---- compile-time inv_freq table (double precision, <1e-14 rel err) ----
constexpr double cexp_taylor(double r) {
    double term = 1.0, sum = 1.0;
    for (int i = 1; i <= 26; ++i) { term *= r / (double)i; sum += term; }
    return sum;
}
constexpr double cexp(double x) {
    double t = x * 1.4426950408889634074;      // x / ln2
    int n = (int)(t >= 0.0 ? t + 0.5 : t - 0.5);
    double r = x - (double)n * 0.69314718055994530942;
    double e = cexp_taylor(r);
    double s = 1.0;
    int m = n < 0 ? -n : n;
    for (int i = 0; i < m; ++i) s *= 2.0;
    return n < 0 ? e / s : e * s;
}
struct alignas(16) FreqTable { float v[D_DIM / 2]; };
constexpr FreqTable make_table() {
    FreqTable t{};
    for (int k = 0; k < D_DIM / 2; ++k) {
        // 10000^(-k/512) = exp(-k * ln(10000)/512)
        t.v[k] = (float)cexp(-(9.2103403719761827361 / 512.0) * (double)k);
    }
    return t;
}
__device__ static const FreqTable g_tab = make_table();

__global__ void __launch_bounds__(256, 3) rope_kernel(
    const float4* __restrict__ x,
    const int* __restrict__ posw,     // raw 32-bit words of token_positions
    float4* __restrict__ out)
{
    // idx over half-rows: s = idx/128, h = idx%128. Thread owns float4
    // columns h and h+128 of row s.
    const int idx = blockIdx.x * 256 + threadIdx.x;   // 0 .. SC/2-1
    const int s   = idx >> 7;                          // sequence position
    const int h   = idx & 127;
    const int i0  = s * COLS + h;                      // column h
    const int i1  = i0 + HALF;                         // column h+128

    // Front-batch all 16 independent 128b loads (8 batches x 2 columns).
    float4 va[B_DIM], vb[B_DIM];
    #pragma unroll
    for (int b = 0; b < B_DIM; b++) va[b] = x[b * SC + i0];
    #pragma unroll
    for (int b = 0; b < B_DIM; b++) vb[b] = x[b * SC + i1];

    // Dtype-robust position read: int64 LE buffer = [0,0,1,0,2,0,..]
    // (word[1]==0), int32 buffer = [0,1,2,..] (word[1]==1).
    const int is64 = (posw[1] == 0);
    const float p = (float)posw[is64 ? (2 * s) : s];

    // inv_freq for pairs (2h, 2h+1) and (2(h+128), 2(h+128)+1)
    const float2 fa = ((const float2*)g_tab.v)[h];
    const float2 fb = ((const float2*)g_tab.v)[h + HALF];

    const float INV_2PI = 0.15915494309189535f;
    const float C1 = 6.28125f;
    const float C2 = 1.9353071795864769e-3f;

    float s0a, c0a, s1a, c1a, s0b, c0b, s1b, c1b;
    {
        float a0 = p * fa.x, a1 = p * fa.y;
        float n0 = rintf(a0 * INV_2PI), n1 = rintf(a1 * INV_2PI);
        float r0 = fmaf(n0, -C1, a0); r0 = fmaf(n0, -C2, r0);
        float r1 = fmaf(n1, -C1, a1); r1 = fmaf(n1, -C2, r1);
        __sincosf(r0, &s0a, &c0a);
        __sincosf(r1, &s1a, &c1a);
    }
    {
        float a0 = p * fb.x, a1 = p * fb.y;
        float n0 = rintf(a0 * INV_2PI), n1 = rintf(a1 * INV_2PI);
        float r0 = fmaf(n0, -C1, a0); r0 = fmaf(n0, -C2, r0);
        float r1 = fmaf(n1, -C1, a1); r1 = fmaf(n1, -C2, r1);
        __sincosf(r0, &s0b, &c0b);
        __sincosf(r1, &s1b, &c1b);
    }

    #pragma unroll
    for (int b = 0; b < B_DIM; b++) {
        float4 o;
        o.x = c0a * va[b].x - s0a * va[b].y;
        o.y = s0a * va[b].x + c0a * va[b].y;
        o.z = c1a * va[b].z - s1a * va[b].w;
        o.w = s1a * va[b].z + c1a * va[b].w;
        out[b * SC + i0] = o;
    }
    #pragma unroll
    for (int b = 0; b < B_DIM; b++) {
        float4 o;
        o.x = c0b * vb[b].x - s0b * vb[b].y;
        o.y = s0b * vb[b].x + c0b * vb[b].y;
        o.z = c1b * vb[b].z - s1b * vb[b].w;
        o.w = s1b * vb[b].z + c1b * vb[b].w;
        out[b * SC + i1] = o;
    }
}

extern "C" void kernel_launch(void* const* d_in, const int* in_sizes, int n_in,
                              void* d_out, int out_size)
{
    // Robust input binding: x has 33,554,432 elements, token_positions 4096.
    const float* xf  = nullptr;
    const int*   pos = nullptr;
    if (n_in >= 2 && in_sizes[0] <= S_DIM) {
        pos = (const int*)d_in[0];
        xf  = (const float*)d_in[1];
    } else {
        xf  = (const float*)d_in[0];
        pos = (const int*)d_in[1];
    }
    float4* out = (float4*)d_out;
    (void)out_size;

    rope_kernel<<<(SC / 2) / 256, 256>>>((const float4*)xf, pos, out);
}

// round 11
// speedup vs baseline: 1.0675x; 1.0014x over previous
#include <cuda_runtime.h>
#include <cuda_bf16.h>

// RoPE: x[8, 4096, 1024] fp32, token_positions[4096] int32/int64.
// FINAL (= R4, the empirical argmin over the full lever matrix):
//  - one thread per float4 (2 rotation pairs) at fixed (s, col)
//  - all 8 batch loads front-batched (MLP=8; 8->16 and 8->4+4 both regress)
//  - DEFAULT cache policy both directions (ldcs/stcs destroy the ~53MB/replay
//    cross-replay L2 reuse measured via DRAM-traffic accounting)
//  - __launch_bounds__(256,4): 56 regs, 40% occ (raising occ regresses)
//  - compile-time DP inv_freq table (no init kernel in the graph)
//  - Cody-Waite 2-term reduction + __sincosf: rel_err 1.7e-7
// Kernel: 35.9us @ 6.0 TB/s, ~215MB DRAM traffic. Mixed-R/W controller
// efficiency is the binding constraint; all perturbations tested regress.

#define S_DIM 4096
#define D_DIM 1024
#define B_DIM 8
#define COLS  (D_DIM / 4)          // 256 float4 columns per row
#define SC    (S_DIM * COLS)       // float4s per batch = 1,048,576

// ---- compile-time inv_freq table (double precision, <1e-14 rel err) ----
constexpr double cexp_taylor(double r) {
    double term = 1.0, sum = 1.0;
    for (int i = 1; i <= 26; ++i) { term *= r / (double)i; sum += term; }
    return sum;
}
constexpr double cexp(double x) {
    double t = x * 1.4426950408889634074;      // x / ln2
    int n = (int)(t >= 0.0 ? t + 0.5 : t - 0.5);
    double r = x - (double)n * 0.69314718055994530942;
    double e = cexp_taylor(r);
    double s = 1.0;
    int m = n < 0 ? -n : n;
    for (int i = 0; i < m; ++i) s *= 2.0;
    return n < 0 ? e / s : e * s;
}
struct alignas(16) FreqTable { float v[D_DIM / 2]; };
constexpr FreqTable make_table() {
    FreqTable t{};
    for (int k = 0; k < D_DIM / 2; ++k) {
        // 10000^(-k/512) = exp(-k * ln(10000)/512)
        t.v[k] = (float)cexp(-(9.2103403719761827361 / 512.0) * (double)k);
    }
    return t;
}
__device__ static const FreqTable g_tab = make_table();

__global__ void __launch_bounds__(256, 4) rope_kernel(
    const float4* __restrict__ x,
    const int* __restrict__ posw,     // raw 32-bit words of token_positions
    float4* __restrict__ out)
{
    const int idx = blockIdx.x * 256 + threadIdx.x;   // 0 .. SC-1
    const int s   = idx >> 8;                          // sequence position
    const int c   = idx & 255;                         // float4 column

    // Front-batch all 8 independent 128b loads (one per batch) so DRAM
    // latency overlaps the trig computation below. Default cache policy.
    float4 v[B_DIM];
    #pragma unroll
    for (int b = 0; b < B_DIM; b++) v[b] = x[b * SC + idx];

    // Dtype-robust position read: int64 LE buffer = [0,0,1,0,2,0,..]
    // (word[1]==0), int32 buffer = [0,1,2,..] (word[1]==1).
    const int is64 = (posw[1] == 0);
    const float p = (float)posw[is64 ? (2 * s) : s];

    // inv_freq for pairs k0=2c, k1=2c+1 (coalesced float2, L2-resident)
    const float2 f = ((const float2*)g_tab.v)[c];

    float a0 = p * f.x;
    float a1 = p * f.y;

    // 2-term Cody-Waite reduction mod 2*pi (n <= 652, n*C1 exact in f32).
    const float INV_2PI = 0.15915494309189535f;
    const float C1 = 6.28125f;
    const float C2 = 1.9353071795864769e-3f;
    float n0 = rintf(a0 * INV_2PI);
    float n1 = rintf(a1 * INV_2PI);
    float r0 = fmaf(n0, -C1, a0); r0 = fmaf(n0, -C2, r0);
    float r1 = fmaf(n1, -C1, a1); r1 = fmaf(n1, -C2, r1);

    float s0, c0, s1, c1;
    __sincosf(r0, &s0, &c0);
    __sincosf(r1, &s1, &c1);

    #pragma unroll
    for (int b = 0; b < B_DIM; b++) {
        float4 o;
        o.x = c0 * v[b].x - s0 * v[b].y;
        o.y = s0 * v[b].x + c0 * v[b].y;
        o.z = c1 * v[b].z - s1 * v[b].w;
        o.w = s1 * v[b].z + c1 * v[b].w;
        out[b * SC + idx] = o;
    }
}

extern "C" void kernel_launch(void* const* d_in, const int* in_sizes, int n_in,
                              void* d_out, int out_size)
{
    // Robust input binding: x has 33,554,432 elements, token_positions 4096.
    const float* xf  = nullptr;
    const int*   pos = nullptr;
    if (n_in >= 2 && in_sizes[0] <= S_DIM) {
        pos = (const int*)d_in[0];
        xf  = (const float*)d_in[1];
    } else {
        xf  = (const float*)d_in[0];
        pos = (const int*)d_in[1];
    }
    float4* out = (float4*)d_out;
    (void)out_size;

    rope_kernel<<<SC / 256, 256>>>((const float4*)xf, pos, out);
}

// round 12
// speedup vs baseline: 1.1051x; 1.0353x over previous
#include <cuda_runtime.h>
#include <cuda_bf16.h>

// RoPE: x[8, 4096, 1024] fp32, token_positions[4096] int32/int64.
// FINAL (= R4, empirical argmin; R11 re-measured this exact code and showed
// +-1.5us run noise, so all remaining "levers" are below the noise floor):
//  - one thread per float4 (2 rotation pairs) at fixed (s, col)
//  - all 8 batch loads front-batched (MLP=8; 16 and 4+4 splits regress)
//  - DEFAULT cache policy both directions (ldcs/stcs destroy the ~53MB/replay
//    cross-replay L2 reuse measured via DRAM-traffic accounting)
//  - __launch_bounds__(256,4): 56 regs, ~41% occ (raising occ never helped)
//  - compile-time DP inv_freq table (no init kernel in the graph)
//  - Cody-Waite 2-term reduction + __sincosf: rel_err 1.7e-7
// Kernel ~35.9-36.6us @ ~5.9TB/s on a 50/50 R/W stream = mixed-direction
// HBM controller ceiling. Plateau confirmed across 8 structural variants.

#define S_DIM 4096
#define D_DIM 1024
#define B_DIM 8
#define COLS  (D_DIM / 4)          // 256 float4 columns per row
#define SC    (S_DIM * COLS)       // float4s per batch = 1,048,576

// ---- compile-time inv_freq table (double precision, <1e-14 rel err) ----
constexpr double cexp_taylor(double r) {
    double term = 1.0, sum = 1.0;
    for (int i = 1; i <= 26; ++i) { term *= r / (double)i; sum += term; }
    return sum;
}
constexpr double cexp(double x) {
    double t = x * 1.4426950408889634074;      // x / ln2
    int n = (int)(t >= 0.0 ? t + 0.5 : t - 0.5);
    double r = x - (double)n * 0.69314718055994530942;
    double e = cexp_taylor(r);
    double s = 1.0;
    int m = n < 0 ? -n : n;
    for (int i = 0; i < m; ++i) s *= 2.0;
    return n < 0 ? e / s : e * s;
}
struct alignas(16) FreqTable { float v[D_DIM / 2]; };
constexpr FreqTable make_table() {
    FreqTable t{};
    for (int k = 0; k < D_DIM / 2; ++k) {
        // 10000^(-k/512) = exp(-k * ln(10000)/512)
        t.v[k] = (float)cexp(-(9.2103403719761827361 / 512.0) * (double)k);
    }
    return t;
}
__device__ static const FreqTable g_tab = make_table();

__global__ void __launch_bounds__(256, 4) rope_kernel(
    const float4* __restrict__ x,
    const int* __restrict__ posw,     // raw 32-bit words of token_positions
    float4* __restrict__ out)
{
    const int idx = blockIdx.x * 256 + threadIdx.x;   // 0 .. SC-1
    const int s   = idx >> 8;                          // sequence position
    const int c   = idx & 255;                         // float4 column

    // Front-batch all 8 independent 128b loads (one per batch) so DRAM
    // latency overlaps the trig computation below. Default cache policy.
    float4 v[B_DIM];
    #pragma unroll
    for (int b = 0; b < B_DIM; b++) v[b] = x[b * SC + idx];

    // Dtype-robust position read: int64 LE buffer = [0,0,1,0,2,0,..]
    // (word[1]==0), int32 buffer = [0,1,2,..] (word[1]==1).
    const int is64 = (posw[1] == 0);
    const float p = (float)posw[is64 ? (2 * s) : s];

    // inv_freq for pairs k0=2c, k1=2c+1 (coalesced float2, L2-resident)
    const float2 f = ((const float2*)g_tab.v)[c];

    float a0 = p * f.x;
    float a1 = p * f.y;

    // 2-term Cody-Waite reduction mod 2*pi (n <= 652, n*C1 exact in f32).
    const float INV_2PI = 0.15915494309189535f;
    const float C1 = 6.28125f;
    const float C2 = 1.9353071795864769e-3f;
    float n0 = rintf(a0 * INV_2PI);
    float n1 = rintf(a1 * INV_2PI);
    float r0 = fmaf(n0, -C1, a0); r0 = fmaf(n0, -C2, r0);
    float r1 = fmaf(n1, -C1, a1); r1 = fmaf(n1, -C2, r1);

    float s0, c0, s1, c1;
    __sincosf(r0, &s0, &c0);
    __sincosf(r1, &s1, &c1);

    #pragma unroll
    for (int b = 0; b < B_DIM; b++) {
        float4 o;
        o.x = c0 * v[b].x - s0 * v[b].y;
        o.y = s0 * v[b].x + c0 * v[b].y;
        o.z = c1 * v[b].z - s1 * v[b].w;
        o.w = s1 * v[b].z + c1 * v[b].w;
        out[b * SC + idx] = o;
    }
}

extern "C" void kernel_launch(void* const* d_in, const int* in_sizes, int n_in,
                              void* d_out, int out_size)
{
    // Robust input binding: x has 33,554,432 elements, token_positions 4096.
    const float* xf  = nullptr;
    const int*   pos = nullptr;
    if (n_in >= 2 && in_sizes[0] <= S_DIM) {
        pos = (const int*)d_in[0];
        xf  = (const float*)d_in[1];
    } else {
        xf  = (const float*)d_in[0];
        pos = (const int*)d_in[1];
    }
    float4* out = (float4*)d_out;
    (void)out_size;

    rope_kernel<<<SC / 256, 256>>>((const float4*)xf, pos, out);
}

// round 13
// speedup vs baseline: 1.1060x; 1.0007x over previous
#include <cuda_runtime.h>
#include <cuda_bf16.h>

// RoPE: x[8, 4096, 1024] fp32, token_positions[4096] int32/int64.
// CONVERGED FINAL (= R4). Three identical-binary measurements: 43.49 / 45.06
// / 43.52 us total (kernel 35.9-36.6us, ~5.9-6.0 TB/s). Nine structural
// variants all measured at-or-below this point:
//  - MLP 2->8 was the only real win (front-batched loads hide DRAM latency);
//    MLP=16 and 4+4 splits regress (L1tex queue saturation / stream breakup)
//  - occupancy 40->50->63% never helped (latency already fully hidden)
//  - __ldcs/__stcs regress: they destroy ~53MB/replay of cross-replay L2
//    reuse (134MB x + write-coalescing vs 126MB L2), default policy wins
//  - persistent single-wave grid regresses (wave transitions already hidden)
// Binding constraint: mixed 50/50 R/W HBM controller efficiency (~75% of
// spec is the ceiling for this stream shape). Compute 6%, issue 13%.
//  - compile-time DP inv_freq table (no init kernel in the graph)
//  - Cody-Waite 2-term reduction + __sincosf: rel_err 1.69e-7

#define S_DIM 4096
#define D_DIM 1024
#define B_DIM 8
#define COLS  (D_DIM / 4)          // 256 float4 columns per row
#define SC    (S_DIM * COLS)       // float4s per batch = 1,048,576

// ---- compile-time inv_freq table (double precision, <1e-14 rel err) ----
constexpr double cexp_taylor(double r) {
    double term = 1.0, sum = 1.0;
    for (int i = 1; i <= 26; ++i) { term *= r / (double)i; sum += term; }
    return sum;
}
constexpr double cexp(double x) {
    double t = x * 1.4426950408889634074;      // x / ln2
    int n = (int)(t >= 0.0 ? t + 0.5 : t - 0.5);
    double r = x - (double)n * 0.69314718055994530942;
    double e = cexp_taylor(r);
    double s = 1.0;
    int m = n < 0 ? -n : n;
    for (int i = 0; i < m; ++i) s *= 2.0;
    return n < 0 ? e / s : e * s;
}
struct alignas(16) FreqTable { float v[D_DIM / 2]; };
constexpr FreqTable make_table() {
    FreqTable t{};
    for (int k = 0; k < D_DIM / 2; ++k) {
        // 10000^(-k/512) = exp(-k * ln(10000)/512)
        t.v[k] = (float)cexp(-(9.2103403719761827361 / 512.0) * (double)k);
    }
    return t;
}
__device__ static const FreqTable g_tab = make_table();

__global__ void __launch_bounds__(256, 4) rope_kernel(
    const float4* __restrict__ x,
    const int* __restrict__ posw,     // raw 32-bit words of token_positions
    float4* __restrict__ out)
{
    const int idx = blockIdx.x * 256 + threadIdx.x;   // 0 .. SC-1
    const int s   = idx >> 8;                          // sequence position
    const int c   = idx & 255;                         // float4 column

    // Front-batch all 8 independent 128b loads (one per batch) so DRAM
    // latency overlaps the trig computation below. Default cache policy.
    float4 v[B_DIM];
    #pragma unroll
    for (int b = 0; b < B_DIM; b++) v[b] = x[b * SC + idx];

    // Dtype-robust position read: int64 LE buffer = [0,0,1,0,2,0,..]
    // (word[1]==0), int32 buffer = [0,1,2,..] (word[1]==1).
    const int is64 = (posw[1] == 0);
    const float p = (float)posw[is64 ? (2 * s) : s];

    // inv_freq for pairs k0=2c, k1=2c+1 (coalesced float2, L2-resident)
    const float2 f = ((const float2*)g_tab.v)[c];

    float a0 = p * f.x;
    float a1 = p * f.y;

    // 2-term Cody-Waite reduction mod 2*pi (n <= 652, n*C1 exact in f32).
    const float INV_2PI = 0.15915494309189535f;
    const float C1 = 6.28125f;
    const float C2 = 1.9353071795864769e-3f;
    float n0 = rintf(a0 * INV_2PI);
    float n1 = rintf(a1 * INV_2PI);
    float r0 = fmaf(n0, -C1, a0); r0 = fmaf(n0, -C2, r0);
    float r1 = fmaf(n1, -C1, a1); r1 = fmaf(n1, -C2, r1);

    float s0, c0, s1, c1;
    __sincosf(r0, &s0, &c0);
    __sincosf(r1, &s1, &c1);

    #pragma unroll
    for (int b = 0; b < B_DIM; b++) {
        float4 o;
        o.x = c0 * v[b].x - s0 * v[b].y;
        o.y = s0 * v[b].x + c0 * v[b].y;
        o.z = c1 * v[b].z - s1 * v[b].w;
        o.w = s1 * v[b].z + c1 * v[b].w;
        out[b * SC + idx] = o;
    }
}

extern "C" void kernel_launch(void* const* d_in, const int* in_sizes, int n_in,
                              void* d_out, int out_size)
{
    // Robust input binding: x has 33,554,432 elements, token_positions 4096.
    const float* xf  = nullptr;
    const int*   pos = nullptr;
    if (n_in >= 2 && in_sizes[0] <= S_DIM) {
        pos = (const int*)d_in[0];
        xf  = (const float*)d_in[1];
    } else {
        xf  = (const float*)d_in[0];
        pos = (const int*)d_in[1];
    }
    float4* out = (float4*)d_out;
    (void)out_size;

    rope_kernel<<<SC / 256, 256>>>((const float4*)xf, pos, out);
}